// round 9
// baseline (speedup 1.0000x reference)
#include <cuda_runtime.h>
#include <math.h>

#define EPSF 1e-7f
#define POS_THR 0.5f
#define NEG_THR 0.4f
#define ALPHA_F 0.25f

#define MAXN 32
#define MAXP 100
#define MAXA 25600

// Contiguous scratch so one memset clears everything that must start at 0.
struct Scratch {
    unsigned long long gtkey[MAXN * MAXP]; // packed (iou_bits<<32)|~a per GT
    double             sumn[MAXN * 3];     // per-batch partial sums
    int                poscnt[MAXN];
    int                done_n[MAXN];       // per-image completed block counters
    int                done;               // completed fixup counter
};
__device__ Scratch g_s;
__device__ float2  g_amax[MAXN * MAXA];    // {maxiou, int_as_float(tix)} per anchor

__device__ __forceinline__ float clipf(float x) {
    return fminf(fmaxf(x, EPSF), 1.0f - EPSF);
}

__device__ __forceinline__ float focal_term(float t, float qraw) {
    float q  = clipf(qraw);
    float pt = t * q + (1.f - t) * (1.f - q);
    float at = t * ALPHA_F + (1.f - t) * (1.f - ALPHA_F);
    float om = 1.f - pt;
    return -at * om * om * __logf(pt);
}

__device__ __forceinline__ float ciou(float4 bt, float4 bp) {
    float ix1 = fmaxf(bt.x, bp.x), iy1 = fmaxf(bt.y, bp.y);
    float ix2 = fminf(bt.z, bp.z), iy2 = fminf(bt.w, bp.w);
    float inter = fmaxf(ix2 - ix1, 0.f) * fmaxf(iy2 - iy1, 0.f);
    float wt = bt.z - bt.x, ht = bt.w - bt.y;
    float wp = bp.z - bp.x, hp = bp.w - bp.y;
    float uni = wt * ht + wp * hp - inter + EPSF;
    float iou = inter / uni;
    float cw = fmaxf(bt.z, bp.z) - fminf(bt.x, bp.x);
    float ch = fmaxf(bt.w, bp.w) - fminf(bt.y, bp.y);
    float c2 = cw * cw + ch * ch + EPSF;
    float dx = bt.x + bt.z - bp.x - bp.z;
    float dy = bt.y + bt.w - bp.y - bp.w;
    float rho2 = (dx * dx + dy * dy) * 0.25f;
    float dat = atanf(wt / (ht + EPSF)) - atanf(wp / (hp + EPSF));
    float v = (4.0f / (float)(M_PI * M_PI)) * dat * dat;
    float alpha = v / (1.0f - iou + v + EPSF);
    return 1.0f - iou + rho2 / c2 + alpha * v;
}

// Per-anchor loss evaluation (shared by both anchors of a thread).
__device__ __forceinline__ void anchor_loss(
    int n, int A, int P, int C, int a, float maxiou, int tix, float4 bt,
    const float* __restrict__ y_true, const float* __restrict__ conf_pred,
    const float* __restrict__ logit_pred, const float4* __restrict__ bbox_pred,
    float& score, float& cls, float& bl, int& posc) {
    bool pos = (maxiou >= POS_THR);
    bool neg = (maxiou < NEG_THR);
    float pc = clipf(conf_pred[(size_t)n * A + a]);
    if (pos)      score += -__logf(pc);
    else if (neg) score += -__logf(1.0f - pc);
    if (pos) {
        posc += 1;
        const float4* qrow = reinterpret_cast<const float4*>(
            logit_pred + ((size_t)n * A + a) * C);
        const float4* trow = reinterpret_cast<const float4*>(
            y_true + ((size_t)n * P + tix) * C);
        for (int c4 = 0; c4 < C / 4; c4++) {
            float4 tv = trow[c4];
            float4 qv = qrow[c4];
            cls += focal_term(tv.x, qv.x) + focal_term(tv.y, qv.y)
                 + focal_term(tv.z, qv.z) + focal_term(tv.w, qv.w);
        }
        bl += ciou(bt, bbox_pred[(size_t)n * A + a]);
    }
}

// ---------------------------------------------------------------------------
// Single fused kernel: 2 anchors/thread, single merged compaction+filter,
// in-kernel per-image fixup + global finalize.
// ---------------------------------------------------------------------------
__global__ void __launch_bounds__(256, 4)
fused_kernel(const float* __restrict__ y_true,
             const float4* __restrict__ bbox_true,
             const float* __restrict__ conf_pred,
             const float* __restrict__ logit_pred,
             const float4* __restrict__ bbox_pred,
             const float4* __restrict__ anchors,
             float* __restrict__ out,
             int N, int P, int A, int C) {
    int n = blockIdx.y;
    int tid = threadIdx.x;
    int a0 = blockIdx.x * 512 + tid;
    int a1 = a0 + 256;
    int lane = tid & 31, warp = tid >> 5;

    __shared__ float4 s_rawgt[MAXP];  // raw GT boxes (original indexing)
    __shared__ float4 s_fgt[MAXP];    // filtered GTs (ascending p)
    __shared__ float  s_farea[MAXP];
    __shared__ short  s_forig[MAXP];  // filtered -> original p
    __shared__ unsigned long long s_key[MAXP];  // filtered-indexed
    __shared__ int    s_wcnt[4];
    __shared__ unsigned s_vmask[4];
    __shared__ int    s_fnv, s_firstv;
    __shared__ float  swx1[8], swy1[8], swx2[8], swy2[8];
    __shared__ float4 s_ubb;

    // Phase A: load anchors, warp union partials, load GT boxes
    float4 an0, an1;
    if (a0 < A) an0 = anchors[a0];
    else { an0.x = 1e30f; an0.y = 1e30f; an0.z = -1e30f; an0.w = -1e30f; }
    if (a1 < A) an1 = anchors[a1];
    else { an1.x = 1e30f; an1.y = 1e30f; an1.z = -1e30f; an1.w = -1e30f; }
    {
        float x1 = fminf(an0.x, an1.x), y1 = fminf(an0.y, an1.y);
        float x2 = fmaxf(an0.z, an1.z), y2 = fmaxf(an0.w, an1.w);
        #pragma unroll
        for (int off = 16; off > 0; off >>= 1) {
            x1 = fminf(x1, __shfl_xor_sync(0xffffffffu, x1, off));
            y1 = fminf(y1, __shfl_xor_sync(0xffffffffu, y1, off));
            x2 = fmaxf(x2, __shfl_xor_sync(0xffffffffu, x2, off));
            y2 = fmaxf(y2, __shfl_xor_sync(0xffffffffu, y2, off));
        }
        if (lane == 0) { swx1[warp] = x1; swy1[warp] = y1; swx2[warp] = x2; swy2[warp] = y2; }
    }
    if (tid < P) {
        s_rawgt[tid] = bbox_true[n * P + tid];
        s_key[tid] = 0ull;
    }
    __syncthreads();

    // Phase B: warp 0 finishes the union
    if (warp == 0) {
        float x1 = (lane < 8) ? swx1[lane] : 1e30f;
        float y1 = (lane < 8) ? swy1[lane] : 1e30f;
        float x2 = (lane < 8) ? swx2[lane] : -1e30f;
        float y2 = (lane < 8) ? swy2[lane] : -1e30f;
        #pragma unroll
        for (int off = 4; off > 0; off >>= 1) {
            x1 = fminf(x1, __shfl_down_sync(0xffffffffu, x1, off));
            y1 = fminf(y1, __shfl_down_sync(0xffffffffu, y1, off));
            x2 = fmaxf(x2, __shfl_down_sync(0xffffffffu, x2, off));
            y2 = fmaxf(y2, __shfl_down_sync(0xffffffffu, y2, off));
        }
        if (lane == 0) { s_ubb.x = x1; s_ubb.y = y1; s_ubb.z = x2; s_ubb.w = y2; }
    }
    __syncthreads();

    // Phase C: merged valid+intersect compaction, plus first-valid tracking
    {
        bool valid = false, keep = false; float4 g = {0,0,0,0};
        float4 ub = s_ubb;
        if (tid < P) {
            g = s_rawgt[tid];
            valid = (g.x > 0.f) || (g.y > 0.f) || (g.z > 0.f) || (g.w > 0.f);
            keep = valid && (g.x < ub.z) && (g.z > ub.x) &&
                            (g.y < ub.w) && (g.w > ub.y);
        }
        if (tid < 128) {
            unsigned mk = __ballot_sync(0xffffffffu, keep);
            unsigned mv = __ballot_sync(0xffffffffu, valid);
            if (lane == 0) { s_wcnt[warp] = __popc(mk); s_vmask[warp] = mv; }
            __syncthreads();
            if (tid == 0) {
                s_fnv = s_wcnt[0] + s_wcnt[1] + s_wcnt[2] + s_wcnt[3];
                int fv = -1;
                for (int w = 0; w < 4 && fv < 0; w++)
                    if (s_vmask[w]) fv = w * 32 + (__ffs(s_vmask[w]) - 1);
                s_firstv = fv;
            }
            int off = 0;
            for (int i = 0; i < warp; i++) off += s_wcnt[i];
            if (keep) {
                int pos = off + __popc(mk & ((1u << lane) - 1u));
                s_fgt[pos] = g;
                s_farea[pos] = (g.z - g.x) * (g.w - g.y);
                s_forig[pos] = (short)tid;
            }
        } else {
            __syncthreads();
        }
        __syncthreads();
    }
    int fnv = s_fnv;
    int firstv = s_firstv;

    float score = 0.f, cls = 0.f, bl = 0.f;
    int posc = 0;

    {
        float area0 = (an0.z - an0.x) * (an0.w - an0.y);
        float area1 = (an1.z - an1.x) * (an1.w - an1.y);
        float bi0 = -1.0f, bd0 = 1.0f, bi1 = -1.0f, bd1 = 1.0f;
        int t0 = 0, t1 = 0;
        unsigned inv_a0 = ~(unsigned)a0, inv_a1 = ~(unsigned)a1;
        #pragma unroll 2
        for (int i = 0; i < fnv; i++) {
            float4 g = s_fgt[i];
            float ab = s_farea[i];
            float iw0 = fmaxf(fminf(an0.z, g.z) - fmaxf(an0.x, g.x), 0.f);
            float ih0 = fmaxf(fminf(an0.w, g.w) - fmaxf(an0.y, g.y), 0.f);
            float in0 = iw0 * ih0;
            float dn0 = area0 + ab - in0 + EPSF;
            if (in0 * bd0 > bi0 * dn0) { bi0 = in0; bd0 = dn0; t0 = i; }
            float iw1 = fmaxf(fminf(an1.z, g.z) - fmaxf(an1.x, g.x), 0.f);
            float ih1 = fmaxf(fminf(an1.w, g.w) - fmaxf(an1.y, g.y), 0.f);
            float in1 = iw1 * ih1;
            float dn1 = area1 + ab - in1 + EPSF;
            if (in1 * bd1 > bi1 * dn1) { bi1 = in1; bd1 = dn1; t1 = i; }
            if (in0 > 0.f || in1 > 0.f) {
                unsigned long long k0 = 0ull, k1 = 0ull;
                if (in0 > 0.f)
                    k0 = ((unsigned long long)__float_as_uint(in0 / dn0) << 32) | inv_a0;
                if (in1 > 0.f)
                    k1 = ((unsigned long long)__float_as_uint(in1 / dn1) << 32) | inv_a1;
                unsigned long long kk = (k0 > k1) ? k0 : k1;
                atomicMax(&s_key[i], kk);
            }
        }
        // resolve per-anchor results
        if (a0 < A) {
            float maxiou; int tix; float4 bt;
            if (fnv > 0)        { maxiou = bi0 / bd0; tix = (int)s_forig[t0]; bt = s_fgt[t0]; }
            else if (firstv>=0) { maxiou = 0.0f; tix = firstv; bt = s_rawgt[firstv]; }
            else                { maxiou = -1.0f; tix = 0; bt = s_rawgt[0]; }
            float2 r; r.x = maxiou; r.y = __int_as_float(tix);
            g_amax[(size_t)n * A + a0] = r;
            anchor_loss(n, A, P, C, a0, maxiou, tix, bt,
                        y_true, conf_pred, logit_pred, bbox_pred,
                        score, cls, bl, posc);
        }
        if (a1 < A) {
            float maxiou; int tix; float4 bt;
            if (fnv > 0)        { maxiou = bi1 / bd1; tix = (int)s_forig[t1]; bt = s_fgt[t1]; }
            else if (firstv>=0) { maxiou = 0.0f; tix = firstv; bt = s_rawgt[firstv]; }
            else                { maxiou = -1.0f; tix = 0; bt = s_rawgt[0]; }
            float2 r; r.x = maxiou; r.y = __int_as_float(tix);
            g_amax[(size_t)n * A + a1] = r;
            anchor_loss(n, A, P, C, a1, maxiou, tix, bt,
                        y_true, conf_pred, logit_pred, bbox_pred,
                        score, cls, bl, posc);
        }
    }
    __syncthreads();
    // per-GT best anchor -> global (filtered-indexed)
    if (tid < fnv && s_key[tid] != 0ull)
        atomicMax(&g_s.gtkey[n * P + (int)s_forig[tid]], s_key[tid]);

    // Block reduction -> per-(n,component) atomics
    unsigned mask = 0xffffffffu;
    #pragma unroll
    for (int off = 16; off > 0; off >>= 1) {
        score += __shfl_down_sync(mask, score, off);
        cls   += __shfl_down_sync(mask, cls, off);
        bl    += __shfl_down_sync(mask, bl, off);
        posc  += __shfl_down_sync(mask, posc, off);
    }
    __shared__ float rs0[8], rs1[8], rs2[8];
    __shared__ int   ri[8];
    if (lane == 0) { rs0[warp] = score; rs1[warp] = cls; rs2[warp] = bl; ri[warp] = posc; }
    __syncthreads();
    if (tid == 0) {
        float q0 = 0.f, q1 = 0.f, q2 = 0.f; int tc = 0;
        for (int w = 0; w < 8; w++) { q0 += rs0[w]; q1 += rs1[w]; q2 += rs2[w]; tc += ri[w]; }
        atomicAdd(&g_s.sumn[n * 3 + 0], (double)q0);
        atomicAdd(&g_s.sumn[n * 3 + 1], (double)q1);
        atomicAdd(&g_s.sumn[n * 3 + 2], (double)q2);
        if (tc) atomicAdd(&g_s.poscnt[n], tc);
    }

    // ------------- per-image completion gate -------------
    __threadfence();
    __shared__ bool s_lastn;
    if (tid == 0) {
        int d = atomicAdd(&g_s.done_n[n], 1);
        s_lastn = (d == (int)gridDim.x - 1);
    }
    __syncthreads();
    if (!s_lastn) return;
    __threadfence();   // all blocks of image n have published gtkey/sums

    // ------------- FIXUP for image n (this block only) -------------
    __shared__ int    s_ba[MAXP + 28];
    __shared__ short  s_wp[MAXP];
    __shared__ int    s_nw;
    __shared__ bool   s_last;

    if (tid < MAXP + 28) s_ba[tid] = -1;
    __syncthreads();
    if (tid < P) {
        unsigned long long key = g_s.gtkey[n * P + tid];
        if (key != 0ull) s_ba[tid] = (int)(~(unsigned)key);
    }
    __syncthreads();

    bool win = false;
    if (tid < P && s_ba[tid] >= 0) {
        int mya = s_ba[tid];
        bool dup = false;
        for (int q = tid + 1; q < P; q++) dup |= (s_ba[q] == mya);
        win = !dup;
    }
    if (tid < 128) {
        unsigned m = __ballot_sync(0xffffffffu, win);
        if (lane == 0) s_wcnt[warp] = __popc(m);
        __syncthreads();
        if (tid == 0) s_nw = s_wcnt[0] + s_wcnt[1] + s_wcnt[2] + s_wcnt[3];
        int off = 0;
        for (int i = 0; i < warp; i++) off += s_wcnt[i];
        if (win) s_wp[off + __popc(m & ((1u << lane) - 1u))] = (short)tid;
    } else {
        __syncthreads();
    }
    __syncthreads();
    int nw = s_nw;

    double d0 = 0.0, d1 = 0.0, d2 = 0.0;
    int dpc = 0;

    for (int wi = warp; wi < nw; wi += (int)blockDim.x >> 5) {
        int p = s_wp[wi];          // new tix
        int ba = s_ba[p];
        float2 am = g_amax[(size_t)n * A + ba];
        float maxiou = am.x;
        int old_tix = __float_as_int(am.y);

        bool pos_t = (maxiou >= POS_THR);
        bool neg_t = (maxiou < NEG_THR);

        if (lane == 0 && !pos_t) {
            float pc = clipf(conf_pred[(size_t)n * A + ba]);
            float ds = -__logf(pc);
            if (neg_t) ds -= -__logf(1.0f - pc);
            d0 += (double)ds;
            dpc += 1;
        }
        if (!pos_t || old_tix != p) {
            const float* qrow = logit_pred + ((size_t)n * A + ba) * C;
            const float* trow_new = y_true + ((size_t)n * P + p) * C;
            const float* trow_old = y_true + ((size_t)n * P + old_tix) * C;
            float dc = 0.f;
            for (int c = lane; c < C; c += 32) {
                float q = qrow[c];
                dc += focal_term(trow_new[c], q);
                if (pos_t) dc -= focal_term(trow_old[c], q);
            }
            #pragma unroll
            for (int off = 16; off > 0; off >>= 1)
                dc += __shfl_down_sync(0xffffffffu, dc, off);
            if (lane == 0) {
                d1 += (double)dc;
                float4 bp = bbox_pred[(size_t)n * A + ba];
                float db = ciou(s_rawgt[p], bp);
                if (pos_t) db -= ciou(s_rawgt[old_tix], bp);
                d2 += (double)db;
            }
        }
    }
    if (lane == 0) {
        if (d0 != 0.0) atomicAdd(&g_s.sumn[n * 3 + 0], d0);
        if (d1 != 0.0) atomicAdd(&g_s.sumn[n * 3 + 1], d1);
        if (d2 != 0.0) atomicAdd(&g_s.sumn[n * 3 + 2], d2);
        if (dpc)       atomicAdd(&g_s.poscnt[n], dpc);
    }
    __syncthreads();
    __threadfence();
    if (tid == 0) {
        int d = atomicAdd(&g_s.done, 1);
        s_last = (d == N - 1);
    }
    __syncthreads();
    if (s_last && tid == 0) {
        __threadfence();
        double af = 0.0, t0 = 0.0, t1 = 0.0, t2 = 0.0;
        for (int nn = 0; nn < N; nn++) {
            int c = g_s.poscnt[nn];
            af += (double)(c > 1 ? c : 1);
            t0 += g_s.sumn[nn * 3 + 0];
            t1 += g_s.sumn[nn * 3 + 1];
            t2 += g_s.sumn[nn * 3 + 2];
        }
        double s[3] = {t0, t1, t2};
        #pragma unroll
        for (int i = 0; i < 3; i++) {
            float v = (float)(s[i] / af);
            if (isnan(v) || isinf(v)) v = 0.f;
            out[i] = v;
        }
    }
}

extern "C" void kernel_launch(void* const* d_in, const int* in_sizes, int n_in,
                              void* d_out, int out_size) {
    const float* y_true    = (const float*)d_in[0];
    const float* bbox_true = (const float*)d_in[1];
    const float* conf_pred = (const float*)d_in[2];
    const float* logit     = (const float*)d_in[3];
    const float* bbox_pred = (const float*)d_in[4];
    const float* anchors   = (const float*)d_in[5];

    int A = in_sizes[5] / 4;
    int N = in_sizes[2] / A;
    int C = in_sizes[3] / (N * A);
    int P = in_sizes[1] / (N * 4);

    void* scratch_addr = nullptr;
    cudaGetSymbolAddress(&scratch_addr, g_s);
    cudaMemsetAsync(scratch_addr, 0, sizeof(Scratch));

    int gx = (A + 511) / 512;
    fused_kernel<<<dim3(gx, N), 256>>>(
        y_true, (const float4*)bbox_true, conf_pred, logit,
        (const float4*)bbox_pred, (const float4*)anchors,
        (float*)d_out, N, P, A, C);
}

// round 11
// speedup vs baseline: 1.6557x; 1.6557x over previous
#include <cuda_runtime.h>
#include <math.h>

#define EPSF 1e-7f
#define POS_THR 0.5f
#define NEG_THR 0.4f
#define ALPHA_F 0.25f

#define MAXN 32
#define MAXP 100
#define MAXA 25600

// Contiguous scratch so one memset clears everything that must start at 0.
struct Scratch {
    unsigned long long gtkey[MAXN * MAXP]; // packed (iou_bits<<32)|~a per GT
    double             sumn[MAXN * 3];     // per-batch partial sums
    int                poscnt[MAXN];
    int                done_n[MAXN];       // per-image completed block counters
    int                done;               // completed fixup counter
};
__device__ Scratch g_s;
__device__ float2  g_amax[MAXN * MAXA];    // {maxiou, int_as_float(tix)} per anchor

__device__ __forceinline__ float clipf(float x) {
    return fminf(fmaxf(x, EPSF), 1.0f - EPSF);
}

__device__ __forceinline__ float focal_term(float t, float qraw) {
    float q  = clipf(qraw);
    float pt = t * q + (1.f - t) * (1.f - q);
    float at = t * ALPHA_F + (1.f - t) * (1.f - ALPHA_F);
    float om = 1.f - pt;
    return -at * om * om * __logf(pt);
}

__device__ __forceinline__ float ciou(float4 bt, float4 bp) {
    float ix1 = fmaxf(bt.x, bp.x), iy1 = fmaxf(bt.y, bp.y);
    float ix2 = fminf(bt.z, bp.z), iy2 = fminf(bt.w, bp.w);
    float inter = fmaxf(ix2 - ix1, 0.f) * fmaxf(iy2 - iy1, 0.f);
    float wt = bt.z - bt.x, ht = bt.w - bt.y;
    float wp = bp.z - bp.x, hp = bp.w - bp.y;
    float uni = wt * ht + wp * hp - inter + EPSF;
    float iou = inter / uni;
    float cw = fmaxf(bt.z, bp.z) - fminf(bt.x, bp.x);
    float ch = fmaxf(bt.w, bp.w) - fminf(bt.y, bp.y);
    float c2 = cw * cw + ch * ch + EPSF;
    float dx = bt.x + bt.z - bp.x - bp.z;
    float dy = bt.y + bt.w - bp.y - bp.w;
    float rho2 = (dx * dx + dy * dy) * 0.25f;
    float dat = atanf(wt / (ht + EPSF)) - atanf(wp / (hp + EPSF));
    float v = (4.0f / (float)(M_PI * M_PI)) * dat * dat;
    float alpha = v / (1.0f - iou + v + EPSF);
    return 1.0f - iou + rho2 / c2 + alpha * v;
}

// ---------------------------------------------------------------------------
// Single fused kernel: per-anchor assignment + losses + per-GT best anchor;
// per-block GT culling; warp-reduced per-GT key updates; in-kernel per-image
// fixup + global finalize. ALL warp collectives run with full participation:
// out-of-range threads carry an empty sentinel anchor (no overlap possible).
// ---------------------------------------------------------------------------
__global__ void __launch_bounds__(256, 6)
fused_kernel(const float* __restrict__ y_true,
             const float4* __restrict__ bbox_true,
             const float* __restrict__ conf_pred,
             const float* __restrict__ logit_pred,
             const float4* __restrict__ bbox_pred,
             const float4* __restrict__ anchors,
             float* __restrict__ out,
             int N, int P, int A, int C) {
    int n = blockIdx.y;
    int tid = threadIdx.x;
    int a = blockIdx.x * blockDim.x + tid;
    int lane = tid & 31, warp = tid >> 5;

    __shared__ float4 s_rawgt[MAXP];  // raw GT boxes (original indexing)
    __shared__ float4 s_fgt[MAXP];    // filtered GTs (ascending p)
    __shared__ float  s_farea[MAXP];
    __shared__ short  s_forig[MAXP];  // filtered -> original p
    __shared__ unsigned long long s_key[MAXP];  // filtered-indexed
    __shared__ int    s_wcnt[4];
    __shared__ int    s_fnv;
    __shared__ float  swx1[8], swy1[8], swx2[8], swy2[8];
    __shared__ float4 s_ubb;

    // Phase A: load anchor (empty sentinel past A), warp union partials, GT load
    float4 an;
    if (a < A) an = anchors[a];
    else { an.x = 1e30f; an.y = 1e30f; an.z = -1e30f; an.w = -1e30f; }
    {
        float x1 = an.x, y1 = an.y, x2 = an.z, y2 = an.w;
        #pragma unroll
        for (int off = 16; off > 0; off >>= 1) {
            x1 = fminf(x1, __shfl_xor_sync(0xffffffffu, x1, off));
            y1 = fminf(y1, __shfl_xor_sync(0xffffffffu, y1, off));
            x2 = fmaxf(x2, __shfl_xor_sync(0xffffffffu, x2, off));
            y2 = fmaxf(y2, __shfl_xor_sync(0xffffffffu, y2, off));
        }
        if (lane == 0) { swx1[warp] = x1; swy1[warp] = y1; swx2[warp] = x2; swy2[warp] = y2; }
    }
    if (tid < P) {
        s_rawgt[tid] = bbox_true[n * P + tid];
        s_key[tid] = 0ull;
    }
    __syncthreads();

    // Phase B: warp 0 finishes the union
    if (warp == 0) {
        float x1 = (lane < 8) ? swx1[lane] : 1e30f;
        float y1 = (lane < 8) ? swy1[lane] : 1e30f;
        float x2 = (lane < 8) ? swx2[lane] : -1e30f;
        float y2 = (lane < 8) ? swy2[lane] : -1e30f;
        #pragma unroll
        for (int off = 4; off > 0; off >>= 1) {
            x1 = fminf(x1, __shfl_down_sync(0xffffffffu, x1, off));
            y1 = fminf(y1, __shfl_down_sync(0xffffffffu, y1, off));
            x2 = fmaxf(x2, __shfl_down_sync(0xffffffffu, x2, off));
            y2 = fmaxf(y2, __shfl_down_sync(0xffffffffu, y2, off));
        }
        if (lane == 0) { s_ubb.x = x1; s_ubb.y = y1; s_ubb.z = x2; s_ubb.w = y2; }
    }
    __syncthreads();

    // Phase C: merged valid+intersect compaction (P <= 128)
    {
        bool keep = false; float4 g = {0,0,0,0};
        float4 ub = s_ubb;
        if (tid < P) {
            g = s_rawgt[tid];
            bool valid = (g.x > 0.f) || (g.y > 0.f) || (g.z > 0.f) || (g.w > 0.f);
            keep = valid && (g.x < ub.z) && (g.z > ub.x) &&
                            (g.y < ub.w) && (g.w > ub.y);
        }
        if (tid < 128) {
            unsigned mk = __ballot_sync(0xffffffffu, keep);
            if (lane == 0) s_wcnt[warp] = __popc(mk);
            __syncthreads();
            if (tid == 0) s_fnv = s_wcnt[0] + s_wcnt[1] + s_wcnt[2] + s_wcnt[3];
            int off = 0;
            for (int i = 0; i < warp; i++) off += s_wcnt[i];
            if (keep) {
                int pos = off + __popc(mk & ((1u << lane) - 1u));
                s_fgt[pos] = g;
                s_farea[pos] = (g.z - g.x) * (g.w - g.y);
                s_forig[pos] = (short)tid;
            }
        } else {
            __syncthreads();
        }
        __syncthreads();
    }
    int fnv = s_fnv;

    float score = 0.f, cls = 0.f, bl = 0.f;
    int posc = 0;

    // Assignment loop: ALL threads participate (sentinel anchors never overlap)
    float areaa = (an.z - an.x) * (an.w - an.y);
    float best = -1.0f;     // rounded-iou argmax, first-index ties (ref-exact)
    int tixc = 0;
    unsigned inv_a = ~(unsigned)a;
    for (int i = 0; i < fnv; i++) {
        float4 g = s_fgt[i];
        float iw = fminf(an.z, g.z) - fmaxf(an.x, g.x);
        float ih = fminf(an.w, g.w) - fmaxf(an.y, g.y);
        unsigned ioub = 0u;
        if (iw > 0.f && ih > 0.f) {
            float inter = iw * ih;
            float denom = areaa + s_farea[i] - inter + EPSF;
            float iou = inter / denom;                 // IEEE, like reference
            if (iou > best) { best = iou; tixc = i; }
            ioub = __float_as_uint(iou);               // iou>0 -> monotone bits
        }
        // warp-wide per-GT key update: single-lane atomic
        if (__any_sync(0xffffffffu, ioub != 0u)) {
            unsigned mx = __reduce_max_sync(0xffffffffu, ioub);
            unsigned winners = __ballot_sync(0xffffffffu, ioub == mx);
            if (lane == (__ffs(winners) - 1)) {
                unsigned long long key = ((unsigned long long)mx << 32) | inv_a;
                atomicMax(&s_key[i], key);
            }
        }
    }

    if (a < A) {
        float maxiou = best;          // -1 when no overlap (thresholds-equiv to 0)
        int tix = (fnv > 0) ? (int)s_forig[tixc] : 0;  // consumed only when pos

        float2 r; r.x = maxiou; r.y = __int_as_float(tix);
        g_amax[(size_t)n * A + a] = r;

        bool pos = (maxiou >= POS_THR);
        bool neg = (maxiou < NEG_THR);

        float pc = clipf(conf_pred[(size_t)n * A + a]);
        if (pos)      score = -__logf(pc);
        else if (neg) score = -__logf(1.0f - pc);

        if (pos) {
            posc = 1;
            const float4* qrow = reinterpret_cast<const float4*>(
                logit_pred + ((size_t)n * A + a) * C);
            const float4* trow = reinterpret_cast<const float4*>(
                y_true + ((size_t)n * P + tix) * C);
            for (int c4 = 0; c4 < C / 4; c4++) {
                float4 tv = trow[c4];
                float4 qv = qrow[c4];
                cls += focal_term(tv.x, qv.x) + focal_term(tv.y, qv.y)
                     + focal_term(tv.z, qv.z) + focal_term(tv.w, qv.w);
            }
            bl = ciou(s_fgt[tixc], bbox_pred[(size_t)n * A + a]);
        }
    }
    __syncthreads();
    // per-GT best anchor -> global (filtered-indexed)
    if (tid < fnv && s_key[tid] != 0ull)
        atomicMax(&g_s.gtkey[n * P + (int)s_forig[tid]], s_key[tid]);

    // Block reduction -> per-(n,component) atomics
    unsigned mask = 0xffffffffu;
    #pragma unroll
    for (int off = 16; off > 0; off >>= 1) {
        score += __shfl_down_sync(mask, score, off);
        cls   += __shfl_down_sync(mask, cls, off);
        bl    += __shfl_down_sync(mask, bl, off);
        posc  += __shfl_down_sync(mask, posc, off);
    }
    __shared__ float rs0[8], rs1[8], rs2[8];
    __shared__ int   ri[8];
    if (lane == 0) { rs0[warp] = score; rs1[warp] = cls; rs2[warp] = bl; ri[warp] = posc; }
    __syncthreads();
    if (tid == 0) {
        float q0 = 0.f, q1 = 0.f, q2 = 0.f; int tc = 0;
        for (int w = 0; w < 8; w++) { q0 += rs0[w]; q1 += rs1[w]; q2 += rs2[w]; tc += ri[w]; }
        atomicAdd(&g_s.sumn[n * 3 + 0], (double)q0);
        atomicAdd(&g_s.sumn[n * 3 + 1], (double)q1);
        atomicAdd(&g_s.sumn[n * 3 + 2], (double)q2);
        if (tc) atomicAdd(&g_s.poscnt[n], tc);
    }

    // ------------- per-image completion gate -------------
    __threadfence();
    __shared__ bool s_lastn;
    if (tid == 0) {
        int d = atomicAdd(&g_s.done_n[n], 1);
        s_lastn = (d == (int)gridDim.x - 1);
    }
    __syncthreads();
    if (!s_lastn) return;
    __threadfence();   // all blocks of image n have published gtkey/sums

    // ------------- FIXUP for image n (this block only) -------------
    __shared__ int    s_ba[MAXP + 28];
    __shared__ short  s_wp[MAXP];
    __shared__ int    s_nw;
    __shared__ bool   s_last;

    if (tid < MAXP + 28) s_ba[tid] = -1;
    __syncthreads();
    if (tid < P) {
        unsigned long long key = g_s.gtkey[n * P + tid];
        if (key != 0ull) s_ba[tid] = (int)(~(unsigned)key);
    }
    __syncthreads();

    bool win = false;
    if (tid < P && s_ba[tid] >= 0) {
        int mya = s_ba[tid];
        bool dup = false;
        for (int q = tid + 1; q < P; q++) dup |= (s_ba[q] == mya);
        win = !dup;
    }
    if (tid < 128) {
        unsigned m = __ballot_sync(0xffffffffu, win);
        if (lane == 0) s_wcnt[warp] = __popc(m);
        __syncthreads();
        if (tid == 0) s_nw = s_wcnt[0] + s_wcnt[1] + s_wcnt[2] + s_wcnt[3];
        int off = 0;
        for (int i = 0; i < warp; i++) off += s_wcnt[i];
        if (win) s_wp[off + __popc(m & ((1u << lane) - 1u))] = (short)tid;
    } else {
        __syncthreads();
    }
    __syncthreads();
    int nw = s_nw;

    double d0 = 0.0, d1 = 0.0, d2 = 0.0;
    int dpc = 0;

    for (int wi = warp; wi < nw; wi += (int)blockDim.x >> 5) {
        int p = s_wp[wi];          // new tix
        int ba = s_ba[p];
        float2 am = g_amax[(size_t)n * A + ba];
        float maxiou = am.x;
        int old_tix = __float_as_int(am.y);

        bool pos_t = (maxiou >= POS_THR);
        bool neg_t = (maxiou < NEG_THR);

        if (lane == 0 && !pos_t) {
            float pc = clipf(conf_pred[(size_t)n * A + ba]);
            float ds = -__logf(pc);
            if (neg_t) ds -= -__logf(1.0f - pc);
            d0 += (double)ds;
            dpc += 1;
        }
        if (!pos_t || old_tix != p) {
            const float* qrow = logit_pred + ((size_t)n * A + ba) * C;
            const float* trow_new = y_true + ((size_t)n * P + p) * C;
            const float* trow_old = y_true + ((size_t)n * P + old_tix) * C;
            float dc = 0.f;
            for (int c = lane; c < C; c += 32) {
                float q = qrow[c];
                dc += focal_term(trow_new[c], q);
                if (pos_t) dc -= focal_term(trow_old[c], q);
            }
            #pragma unroll
            for (int off = 16; off > 0; off >>= 1)
                dc += __shfl_down_sync(0xffffffffu, dc, off);
            if (lane == 0) {
                d1 += (double)dc;
                float4 bp = bbox_pred[(size_t)n * A + ba];
                float db = ciou(s_rawgt[p], bp);
                if (pos_t) db -= ciou(s_rawgt[old_tix], bp);
                d2 += (double)db;
            }
        }
    }
    if (lane == 0) {
        if (d0 != 0.0) atomicAdd(&g_s.sumn[n * 3 + 0], d0);
        if (d1 != 0.0) atomicAdd(&g_s.sumn[n * 3 + 1], d1);
        if (d2 != 0.0) atomicAdd(&g_s.sumn[n * 3 + 2], d2);
        if (dpc)       atomicAdd(&g_s.poscnt[n], dpc);
    }
    __syncthreads();
    __threadfence();
    if (tid == 0) {
        int d = atomicAdd(&g_s.done, 1);
        s_last = (d == N - 1);
    }
    __syncthreads();
    if (s_last && tid == 0) {
        __threadfence();
        double af = 0.0, t0 = 0.0, t1 = 0.0, t2 = 0.0;
        for (int nn = 0; nn < N; nn++) {
            int c = g_s.poscnt[nn];
            af += (double)(c > 1 ? c : 1);
            t0 += g_s.sumn[nn * 3 + 0];
            t1 += g_s.sumn[nn * 3 + 1];
            t2 += g_s.sumn[nn * 3 + 2];
        }
        double s[3] = {t0, t1, t2};
        #pragma unroll
        for (int i = 0; i < 3; i++) {
            float v = (float)(s[i] / af);
            if (isnan(v) || isinf(v)) v = 0.f;
            out[i] = v;
        }
    }
}

extern "C" void kernel_launch(void* const* d_in, const int* in_sizes, int n_in,
                              void* d_out, int out_size) {
    const float* y_true    = (const float*)d_in[0];
    const float* bbox_true = (const float*)d_in[1];
    const float* conf_pred = (const float*)d_in[2];
    const float* logit     = (const float*)d_in[3];
    const float* bbox_pred = (const float*)d_in[4];
    const float* anchors   = (const float*)d_in[5];

    int A = in_sizes[5] / 4;
    int N = in_sizes[2] / A;
    int C = in_sizes[3] / (N * A);
    int P = in_sizes[1] / (N * 4);

    void* scratch_addr = nullptr;
    cudaGetSymbolAddress(&scratch_addr, g_s);
    cudaMemsetAsync(scratch_addr, 0, sizeof(Scratch));

    int gx = (A + 255) / 256;
    fused_kernel<<<dim3(gx, N), 256>>>(
        y_true, (const float4*)bbox_true, conf_pred, logit,
        (const float4*)bbox_pred, (const float4*)anchors,
        (float*)d_out, N, P, A, C);
}